// round 4
// baseline (speedup 1.0000x reference)
#include <cuda_runtime.h>

#define NP 8192
#define NG 128
#define NGNG (NG * NG)
#define KSPLIT 74          // 2*74 = 148 blocks = one full wave
#define CHUNK 8
#define NTHREADS 1024
#define NSPLIT2 8

typedef unsigned long long u64;

// K-split partial sums: [ks][ch][y*128+x]
__device__ float g_part[KSPLIT * 3 * NGNG];
// Stage-1 reduce output: [ch][split][g]
__device__ float g_p2[3 * NSPLIT2 * NGNG];

#define FMA2(d, a, b) asm("fma.rn.f32x2 %0, %1, %2, %0;" : "+l"(d) : "l"(a), "l"(b))
#define UNPACK2(lo, hi, s) asm("mov.b64 {%0, %1}, %2;" : "=r"(lo), "=r"(hi) : "l"(s))

// ---------------------------------------------------------------------------
// Fused triple GEMM S_c[x][y] = sum_k Ex[x][k] * B_c[y][k], f32x2 FMAs.
// A packed as adjacent-m pairs (direct LDS.64, no PACK), B stored duplicated
// so one LDS.128 feeds both n-columns of a thread. 1024 thr, 32 warps/SM.
// Grid: 148 blocks = 2 N-tiles x 74 K-slices.
// ---------------------------------------------------------------------------
__global__ void __launch_bounds__(NTHREADS, 1) main_kernel(
    const float* __restrict__ X, const float* __restrict__ Y) {

    // A: [k][m], m contiguous so (2tm, 2tm+1) is one aligned 8B pair
    __shared__ __align__(16) float As[2][CHUNK][NG + 2];
    // B duplicated: [ch][k][2n..2n+1] both hold b_c[n]; 64 n -> 128 floats
    __shared__ __align__(16) float Bd[2][3][CHUNK][NG];

    const float GSTEP = 4.0f / 127.0f;
    int b = blockIdx.x;
    int ks    = b >> 1;
    int tileN = (b & 1) * 64;
    int tid = threadIdx.x;
    int tm = tid & 31;     // m pairs at 2tm and 2tm+64
    int tn = tid >> 5;     // n pair: 2tn, 2tn+1  (0..31)

    const float2* Xv = (const float2*)X;
    const float2* Yv = (const float2*)Y;

    u64 acc[3][2][2];      // [ch][m-pair][n]
    #pragma unroll
    for (int c = 0; c < 3; c++)
        #pragma unroll
        for (int r = 0; r < 2; r++) { acc[c][r][0] = 0ull; acc[c][r][1] = 0ull; }

    int kbeg = (ks * NP) / KSPLIT;
    int kend = ((ks + 1) * NP) / KSPLIT;
    int nch = (kend - kbeg + CHUNK - 1) / CHUNK;

    auto fill = [&](int buf, int k0) {
        int rem = kend - k0;
        // A: 128 m x 8 k = 1024 entries, 1 per thread
        {
            int m = tid & 127, kk = tid >> 7;
            float ex = 0.0f;
            if (kk < rem) {
                float2 xv = Xv[k0 + kk];
                float dx = fmaf((float)m, GSTEP, -2.0f) - xv.x;
                ex = __expf(-0.5f * dx * dx);
            }
            As[buf][kk][m] = ex;
        }
        // B: 64 n x 8 k = 512 entries, first 512 threads, duplicated store
        if (tid < 512) {
            int n = tid & 63, kk = tid >> 6;
            float ey = 0.0f, y0 = 0.0f, y1 = 0.0f;
            if (kk < rem) {
                float2 xv = Xv[k0 + kk];
                float2 yv = Yv[k0 + kk];
                float dy = fmaf((float)(tileN + n), GSTEP, -2.0f) - xv.y;
                ey = __expf(-0.5f * dy * dy);
                y0 = yv.x; y1 = yv.y;
            }
            float b1v = ey * y0, b2v = ey * y1;
            Bd[buf][0][kk][2 * n]     = ey;
            Bd[buf][0][kk][2 * n + 1] = ey;
            Bd[buf][1][kk][2 * n]     = b1v;
            Bd[buf][1][kk][2 * n + 1] = b1v;
            Bd[buf][2][kk][2 * n]     = b2v;
            Bd[buf][2][kk][2 * n + 1] = b2v;
        }
    };

    fill(0, kbeg);
    __syncthreads();

    for (int c = 0; c < nch; c++) {
        int buf = c & 1;
        if (c + 1 < nch) fill(buf ^ 1, kbeg + (c + 1) * CHUNK);

        #pragma unroll
        for (int k = 0; k < CHUNK; k++) {
            u64 a0 = *reinterpret_cast<const u64*>(&As[buf][k][2 * tm]);
            u64 a1 = *reinterpret_cast<const u64*>(&As[buf][k][2 * tm + 64]);
            // whole warp same address -> broadcast; 16B = both dup'd n values
            ulonglong2 b0 = *reinterpret_cast<const ulonglong2*>(&Bd[buf][0][k][4 * tn]);
            ulonglong2 b1 = *reinterpret_cast<const ulonglong2*>(&Bd[buf][1][k][4 * tn]);
            ulonglong2 b2 = *reinterpret_cast<const ulonglong2*>(&Bd[buf][2][k][4 * tn]);
            FMA2(acc[0][0][0], a0, b0.x); FMA2(acc[0][0][1], a0, b0.y);
            FMA2(acc[0][1][0], a1, b0.x); FMA2(acc[0][1][1], a1, b0.y);
            FMA2(acc[1][0][0], a0, b1.x); FMA2(acc[1][0][1], a0, b1.y);
            FMA2(acc[1][1][0], a1, b1.x); FMA2(acc[1][1][1], a1, b1.y);
            FMA2(acc[2][0][0], a0, b2.x); FMA2(acc[2][0][1], a0, b2.y);
            FMA2(acc[2][1][0], a1, b2.x); FMA2(acc[2][1][1], a1, b2.y);
        }
        __syncthreads();
    }

    // Write partials as 8B pairs (m, m+1 contiguous): [ks][ch][n*128 + m]
    float* base = g_part + ks * 3 * NGNG;
    #pragma unroll
    for (int c = 0; c < 3; c++) {
        #pragma unroll
        for (int r = 0; r < 2; r++) {
            int m = 2 * tm + 64 * r;
            #pragma unroll
            for (int nn = 0; nn < 2; nn++) {
                int n = tileN + 2 * tn + nn;
                *reinterpret_cast<u64*>(&base[c * NGNG + n * NG + m]) = acc[c][r][nn];
            }
        }
    }
}

// ---------------------------------------------------------------------------
// Reduce stage 1: 131072 threads; thread (g, s) sums ~9-10 slices x 3 ch.
// ---------------------------------------------------------------------------
__global__ void __launch_bounds__(256) reduce1_kernel() {
    int idx = blockIdx.x * 256 + threadIdx.x;
    int g = idx & (NGNG - 1);
    int s = idx >> 14;
    int b0 = (s * KSPLIT) >> 3;
    int b1 = ((s + 1) * KSPLIT) >> 3;

    float s0 = 0.0f, s1 = 0.0f, s2 = 0.0f;
    const float* p = g_part + b0 * 3 * NGNG + g;
    #pragma unroll 5
    for (int ks = b0; ks < b1; ks++, p += 3 * NGNG) {
        s0 += p[0];
        s1 += p[NGNG];
        s2 += p[2 * NGNG];
    }
    g_p2[(0 * NSPLIT2 + s) * NGNG + g] = s0;
    g_p2[(1 * NSPLIT2 + s) * NGNG + g] = s1;
    g_p2[(2 * NSPLIT2 + s) * NGNG + g] = s2;
}

// ---------------------------------------------------------------------------
// Reduce stage 2: sum 8 splits per channel, normalize, write.
// ---------------------------------------------------------------------------
__global__ void __launch_bounds__(256) reduce2_kernel(float* __restrict__ out) {
    int g = blockIdx.x * 256 + threadIdx.x;
    float t0 = 0.0f, t1 = 0.0f, t2 = 0.0f;
    #pragma unroll
    for (int s = 0; s < NSPLIT2; s++) {
        t0 += g_p2[(0 * NSPLIT2 + s) * NGNG + g];
        t1 += g_p2[(1 * NSPLIT2 + s) * NGNG + g];
        t2 += g_p2[(2 * NSPLIT2 + s) * NGNG + g];
    }
    float inv = 1.0f / t0;
    out[g]            = t0;
    out[NGNG + g]     = t1 * inv;
    out[2 * NGNG + g] = t2 * inv;
}

extern "C" void kernel_launch(void* const* d_in, const int* in_sizes, int n_in,
                              void* d_out, int out_size) {
    const float* X = (const float*)d_in[0];
    const float* Y = (const float*)d_in[1];
    float* out = (float*)d_out;

    main_kernel<<<2 * KSPLIT, NTHREADS>>>(X, Y);
    reduce1_kernel<<<NSPLIT2 * NGNG / 256, 256>>>();
    reduce2_kernel<<<NGNG / 256, 256>>>(out);
}

// round 6
// speedup vs baseline: 1.4141x; 1.4141x over previous
#include <cuda_runtime.h>
#include <cuda_bf16.h>
#include <cstdint>

#define NP 8192
#define NG 128
#define NGNG (NG * NG)
#define KSPLIT 128
#define KSLICE 64
#define NSPLIT2 8

// smem byte offsets (dynamic, 64KB total)
#define A_HI 0
#define A_LO 16384
#define B_HI 32768
#define B_LO 49152
#define SMEM_TOTAL 65536

__device__ float g_part[KSPLIT * 3 * NGNG];   // [ks][ch][n*128+m]
__device__ float g_p2[3 * NSPLIT2 * NGNG];

#define SWZ(o) ((o) ^ (((o) >> 3) & 0x70))

__device__ __forceinline__ uint32_t smem_u32(const void* p) {
    uint32_t a;
    asm("{ .reg .u64 t; cvta.to.shared.u64 t, %1; cvt.u32.u64 %0, t; }"
        : "=r"(a) : "l"(p));
    return a;
}
__device__ __forceinline__ void ldsm4(uint32_t& r0, uint32_t& r1,
                                      uint32_t& r2, uint32_t& r3, uint32_t a) {
    asm volatile("ldmatrix.sync.aligned.m8n8.x4.shared.b16 {%0,%1,%2,%3}, [%4];"
                 : "=r"(r0), "=r"(r1), "=r"(r2), "=r"(r3) : "r"(a));
}
__device__ __forceinline__ void mma16816(float* d, const uint32_t* a,
                                         const uint32_t* b) {
    asm volatile(
        "mma.sync.aligned.m16n8k16.row.col.f32.bf16.bf16.f32 "
        "{%0,%1,%2,%3},{%4,%5,%6,%7},{%8,%9},{%0,%1,%2,%3};"
        : "+f"(d[0]), "+f"(d[1]), "+f"(d[2]), "+f"(d[3])
        : "r"(a[0]), "r"(a[1]), "r"(a[2]), "r"(a[3]), "r"(b[0]), "r"(b[1]));
}

// ---------------------------------------------------------------------------
// Main: block (ch, ks) computes 128x128 partial S_ch for one 64-k slice via
// bf16 hi/lo split HMMA (3 passes: ah*bh + ah*bl + al*bh), fp32 accum.
// ---------------------------------------------------------------------------
__global__ void __launch_bounds__(512, 1) main_kernel(
    const float* __restrict__ X, const float* __restrict__ Y) {
    extern __shared__ char smem[];
    uint32_t sb = smem_u32(smem);
    int tid = threadIdx.x, lane = tid & 31, wid = tid >> 5;
    int bx = blockIdx.x;
    int ks = bx & 127, ch = bx >> 7;
    int kbeg = ks * KSLICE;

    const float GSTEP = 4.0f / 127.0f;
    const float2* Xv = (const float2*)X;
    const float2* Yv = (const float2*)Y;

    // ---- Build A tables: Ex[m][k] hi/lo (SW128-swizzled 128B rows) --------
    #pragma unroll
    for (int it = 0; it < 16; it++) {
        int idx = it * 512 + tid;
        int kk = idx & 63, m = idx >> 6;
        float2 xv = Xv[kbeg + kk];
        float dx = fmaf((float)m, GSTEP, -2.0f) - xv.x;
        float ex = __expf(-0.5f * dx * dx);
        __nv_bfloat16 h = __float2bfloat16(ex);
        __nv_bfloat16 l = __float2bfloat16(ex - __bfloat162float(h));
        uint32_t sw = SWZ((uint32_t)(m * 128 + kk * 2));
        *(__nv_bfloat16*)(smem + A_HI + sw) = h;
        *(__nv_bfloat16*)(smem + A_LO + sw) = l;
    }
    // ---- Build B tables for this channel: (Ey * psi_ch)[n][k] hi/lo -------
    #pragma unroll
    for (int it = 0; it < 16; it++) {
        int idx = it * 512 + tid;
        int kk = idx & 63, n = idx >> 6;
        float2 xv = Xv[kbeg + kk];
        float dy = fmaf((float)n, GSTEP, -2.0f) - xv.y;
        float val = __expf(-0.5f * dy * dy);
        if (ch) {
            float2 yv = Yv[kbeg + kk];
            val *= (ch == 1 ? yv.x : yv.y);
        }
        __nv_bfloat16 h = __float2bfloat16(val);
        __nv_bfloat16 l = __float2bfloat16(val - __bfloat162float(h));
        uint32_t sw = SWZ((uint32_t)(n * 128 + kk * 2));
        *(__nv_bfloat16*)(smem + B_HI + sw) = h;
        *(__nv_bfloat16*)(smem + B_LO + sw) = l;
    }
    __syncthreads();

    // ---- Warp tiling: 16 warps in 4x4; warp tile 32x32 ---------------------
    int wm = (wid & 3) * 32, wn = (wid >> 2) * 32;
    int arow = lane & 15;
    uint32_t acolx = (uint32_t)((lane >> 4) << 4);
    int brow = (lane & 7) + ((lane & 16) ? 8 : 0);
    uint32_t bcolx = (lane & 8) ? 16u : 0u;
    uint32_t axor = (uint32_t)((arow & 7) << 4);
    uint32_t bxor = (uint32_t)((lane & 7) << 4);

    float acc[2][4][4];
    #pragma unroll
    for (int i = 0; i < 2; i++)
        #pragma unroll
        for (int j = 0; j < 4; j++)
            #pragma unroll
            for (int c = 0; c < 4; c++) acc[i][j][c] = 0.0f;

    #pragma unroll
    for (int split = 0; split < 3; split++) {
        uint32_t Aoff = (split == 2) ? A_LO : A_HI;
        uint32_t Boff = (split == 1) ? B_LO : B_HI;
        uint32_t ab0 = sb + Aoff + (uint32_t)((wm + arow) * 128);
        uint32_t ab1 = sb + Aoff + (uint32_t)((wm + 16 + arow) * 128);
        uint32_t bb0 = sb + Boff + (uint32_t)((wn + brow) * 128);
        uint32_t bb1 = sb + Boff + (uint32_t)((wn + 16 + brow) * 128);

        #pragma unroll
        for (int kstep = 0; kstep < 4; kstep++) {
            uint32_t acol = (uint32_t)(kstep * 32 + acolx) ^ axor;
            uint32_t bcol = (uint32_t)(kstep * 32 + bcolx) ^ bxor;
            uint32_t a0[4], a1[4], bf[4][2];
            ldsm4(a0[0], a0[1], a0[2], a0[3], ab0 + acol);
            ldsm4(a1[0], a1[1], a1[2], a1[3], ab1 + acol);
            ldsm4(bf[0][0], bf[0][1], bf[1][0], bf[1][1], bb0 + bcol);
            ldsm4(bf[2][0], bf[2][1], bf[3][0], bf[3][1], bb1 + bcol);
            #pragma unroll
            for (int nt = 0; nt < 4; nt++) {
                mma16816(acc[0][nt], a0, bf[nt]);
                mma16816(acc[1][nt], a1, bf[nt]);
            }
        }
    }

    // ---- Epilogue: fp32 partials to g_part[ks][ch][n*128+m] ----------------
    float* base = g_part + (ks * 3 + ch) * NGNG;
    int quad = lane >> 2, tq = lane & 3;
    #pragma unroll
    for (int mt = 0; mt < 2; mt++) {
        #pragma unroll
        for (int nt = 0; nt < 4; nt++) {
            int m = wm + mt * 16 + quad;
            int n = wn + nt * 8 + 2 * tq;
            base[n * NG + m]           = acc[mt][nt][0];
            base[(n + 1) * NG + m]     = acc[mt][nt][1];
            base[n * NG + m + 8]       = acc[mt][nt][2];
            base[(n + 1) * NG + m + 8] = acc[mt][nt][3];
        }
    }
}

// ---------------------------------------------------------------------------
// Reduce stage 1: 131072 threads; (g, s) sums 16 slices x 3 ch.
// ---------------------------------------------------------------------------
__global__ void __launch_bounds__(256) reduce1_kernel() {
    int idx = blockIdx.x * 256 + threadIdx.x;
    int g = idx & (NGNG - 1);
    int s = idx >> 14;
    int b0 = s * (KSPLIT / NSPLIT2);
    int b1 = b0 + (KSPLIT / NSPLIT2);

    float s0 = 0.0f, s1 = 0.0f, s2 = 0.0f;
    const float* p = g_part + b0 * 3 * NGNG + g;
    #pragma unroll 4
    for (int k = b0; k < b1; k++, p += 3 * NGNG) {
        s0 += p[0];
        s1 += p[NGNG];
        s2 += p[2 * NGNG];
    }
    g_p2[(0 * NSPLIT2 + s) * NGNG + g] = s0;
    g_p2[(1 * NSPLIT2 + s) * NGNG + g] = s1;
    g_p2[(2 * NSPLIT2 + s) * NGNG + g] = s2;
}

// ---------------------------------------------------------------------------
// Reduce stage 2: sum 8 splits per channel, normalize, write.
// ---------------------------------------------------------------------------
__global__ void __launch_bounds__(256) reduce2_kernel(float* __restrict__ out) {
    int g = blockIdx.x * 256 + threadIdx.x;
    float t0 = 0.0f, t1 = 0.0f, t2 = 0.0f;
    #pragma unroll
    for (int s = 0; s < NSPLIT2; s++) {
        t0 += g_p2[(0 * NSPLIT2 + s) * NGNG + g];
        t1 += g_p2[(1 * NSPLIT2 + s) * NGNG + g];
        t2 += g_p2[(2 * NSPLIT2 + s) * NGNG + g];
    }
    float inv = 1.0f / t0;
    out[g]            = t0;
    out[NGNG + g]     = t1 * inv;
    out[2 * NGNG + g] = t2 * inv;
}

extern "C" void kernel_launch(void* const* d_in, const int* in_sizes, int n_in,
                              void* d_out, int out_size) {
    const float* X = (const float*)d_in[0];
    const float* Y = (const float*)d_in[1];
    float* out = (float*)d_out;

    cudaFuncSetAttribute(main_kernel,
                         cudaFuncAttributeMaxDynamicSharedMemorySize, SMEM_TOTAL);
    main_kernel<<<3 * KSPLIT, 512, SMEM_TOTAL>>>(X, Y);
    reduce1_kernel<<<NSPLIT2 * NGNG / 256, 256>>>();
    reduce2_kernel<<<NGNG / 256, 256>>>(out);
}

// round 7
// speedup vs baseline: 1.5577x; 1.1015x over previous
#include <cuda_runtime.h>
#include <cuda_bf16.h>
#include <cstdint>

#define NP 8192
#define NG 128
#define NGNG (NG * NG)
#define KSPLIT 128
#define KSLICE 64

// smem byte offsets (dynamic, 128KB total)
#define A_HI 0
#define A_LO 16384
#define B_T(ch, p) (32768 + ((ch) * 2 + (p)) * 16384)
#define SMEM_TOTAL 131072

__device__ float g_part[KSPLIT * 3 * NGNG];   // [ks][ch][n*128+m]

#define SWZ(o) ((o) ^ (((o) >> 3) & 0x70))

__device__ __forceinline__ uint32_t smem_u32(const void* p) {
    uint32_t a;
    asm("{ .reg .u64 t; cvta.to.shared.u64 t, %1; cvt.u32.u64 %0, t; }"
        : "=r"(a) : "l"(p));
    return a;
}
__device__ __forceinline__ void ldsm4(uint32_t& r0, uint32_t& r1,
                                      uint32_t& r2, uint32_t& r3, uint32_t a) {
    asm volatile("ldmatrix.sync.aligned.m8n8.x4.shared.b16 {%0,%1,%2,%3}, [%4];"
                 : "=r"(r0), "=r"(r1), "=r"(r2), "=r"(r3) : "r"(a));
}
__device__ __forceinline__ void mma16816(float* d, const uint32_t* a,
                                         const uint32_t* b) {
    asm volatile(
        "mma.sync.aligned.m16n8k16.row.col.f32.bf16.bf16.f32 "
        "{%0,%1,%2,%3},{%4,%5,%6,%7},{%8,%9},{%0,%1,%2,%3};"
        : "+f"(d[0]), "+f"(d[1]), "+f"(d[2]), "+f"(d[3])
        : "r"(a[0]), "r"(a[1]), "r"(a[2]), "r"(a[3]), "r"(b[0]), "r"(b[1]));
}
__device__ __forceinline__ uint32_t pack_bf16(float a, float b) {
    uint16_t lo = __bfloat16_as_ushort(__float2bfloat16(a));
    uint16_t hi = __bfloat16_as_ushort(__float2bfloat16(b));
    return (uint32_t)lo | ((uint32_t)hi << 16);
}

// ---------------------------------------------------------------------------
// Main: block ks builds A hi/lo once + 3 channel B tables (ey computed once),
// then 3 channels x 3 splits x 4 ksteps of m16n8k16 bf16 HMMA, fp32 accum.
// Grid 128 = one wave. 512 threads, warp grid 4m x 4n, warp tile 32x32.
// ---------------------------------------------------------------------------
__global__ void __launch_bounds__(512, 1) main_kernel(
    const float* __restrict__ X, const float* __restrict__ Y) {
    extern __shared__ char smem[];
    uint32_t sb = smem_u32(smem);
    int tid = threadIdx.x, lane = tid & 31, wid = tid >> 5;
    int ks = blockIdx.x;
    int kbeg = ks * KSLICE;

    const float GSTEP = 4.0f / 127.0f;
    const float2* Xv = (const float2*)X;
    const float2* Yv = (const float2*)Y;

    // ---- Build A: Ex[m][k] hi/lo, k-pairs packed, SW128 rows --------------
    #pragma unroll
    for (int it = 0; it < 8; it++) {
        int idx = it * 512 + tid;            // 4096 items: 128 m x 32 kpairs
        int kp = idx & 31, m = idx >> 5;
        int kk = 2 * kp;
        float2 x0 = Xv[kbeg + kk];
        float2 x1 = Xv[kbeg + kk + 1];
        float gm = fmaf((float)m, GSTEP, -2.0f);
        float d0 = gm - x0.x, d1 = gm - x1.x;
        float e0 = __expf(-0.5f * d0 * d0);
        float e1 = __expf(-0.5f * d1 * d1);
        float h0 = __bfloat162float(__float2bfloat16(e0));
        float h1 = __bfloat162float(__float2bfloat16(e1));
        uint32_t sw = SWZ((uint32_t)(m * 128 + kk * 2));
        *(uint32_t*)(smem + A_HI + sw) = pack_bf16(h0, h1);
        *(uint32_t*)(smem + A_LO + sw) = pack_bf16(e0 - h0, e1 - h1);
    }
    // ---- Build B: ey once, 3 channel tables hi/lo --------------------------
    #pragma unroll
    for (int it = 0; it < 8; it++) {
        int idx = it * 512 + tid;            // 4096 items: 128 n x 32 kpairs
        int kp = idx & 31, n = idx >> 5;
        int kk = 2 * kp;
        float2 x0 = Xv[kbeg + kk];
        float2 x1 = Xv[kbeg + kk + 1];
        float2 y0 = Yv[kbeg + kk];
        float2 y1 = Yv[kbeg + kk + 1];
        float gn = fmaf((float)n, GSTEP, -2.0f);
        float d0 = gn - x0.y, d1 = gn - x1.y;
        float e0 = __expf(-0.5f * d0 * d0);
        float e1 = __expf(-0.5f * d1 * d1);
        uint32_t sw = SWZ((uint32_t)(n * 128 + kk * 2));
        float v0[3] = { e0, e0 * y0.x, e0 * y0.y };
        float v1[3] = { e1, e1 * y1.x, e1 * y1.y };
        #pragma unroll
        for (int c = 0; c < 3; c++) {
            float h0 = __bfloat162float(__float2bfloat16(v0[c]));
            float h1 = __bfloat162float(__float2bfloat16(v1[c]));
            *(uint32_t*)(smem + B_T(c, 0) + sw) = pack_bf16(h0, h1);
            *(uint32_t*)(smem + B_T(c, 1) + sw) = pack_bf16(v0[c] - h0, v1[c] - h1);
        }
    }
    __syncthreads();

    // ---- Warp tiling (identical frag scheme to R6, which verified) --------
    int wm = (wid & 3) * 32, wn = (wid >> 2) * 32;
    int arow = lane & 15;
    uint32_t acolx = (uint32_t)((lane >> 4) << 4);
    int brow = (lane & 7) + ((lane & 16) ? 8 : 0);
    uint32_t bcolx = (lane & 8) ? 16u : 0u;
    uint32_t axor = (uint32_t)((arow & 7) << 4);
    uint32_t bxor = (uint32_t)((lane & 7) << 4);
    int quad = lane >> 2, tq = lane & 3;

    #pragma unroll 1
    for (int ch = 0; ch < 3; ch++) {
        float acc[2][4][4];
        #pragma unroll
        for (int i = 0; i < 2; i++)
            #pragma unroll
            for (int j = 0; j < 4; j++)
                #pragma unroll
                for (int c = 0; c < 4; c++) acc[i][j][c] = 0.0f;

        #pragma unroll
        for (int split = 0; split < 3; split++) {
            uint32_t Aoff = (split == 2) ? A_LO : A_HI;
            uint32_t Boff = B_T(ch, (split == 1) ? 1 : 0);
            uint32_t ab0 = sb + Aoff + (uint32_t)((wm + arow) * 128);
            uint32_t ab1 = sb + Aoff + (uint32_t)((wm + 16 + arow) * 128);
            uint32_t bb0 = sb + Boff + (uint32_t)((wn + brow) * 128);
            uint32_t bb1 = sb + Boff + (uint32_t)((wn + 16 + brow) * 128);

            #pragma unroll
            for (int kstep = 0; kstep < 4; kstep++) {
                uint32_t acol = (uint32_t)(kstep * 32 + acolx) ^ axor;
                uint32_t bcol = (uint32_t)(kstep * 32 + bcolx) ^ bxor;
                uint32_t a0[4], a1[4], bf[4][2];
                ldsm4(a0[0], a0[1], a0[2], a0[3], ab0 + acol);
                ldsm4(a1[0], a1[1], a1[2], a1[3], ab1 + acol);
                ldsm4(bf[0][0], bf[0][1], bf[1][0], bf[1][1], bb0 + bcol);
                ldsm4(bf[2][0], bf[2][1], bf[3][0], bf[3][1], bb1 + bcol);
                #pragma unroll
                for (int nt = 0; nt < 4; nt++) {
                    mma16816(acc[0][nt], a0, bf[nt]);
                    mma16816(acc[1][nt], a1, bf[nt]);
                }
            }
        }

        // Epilogue: fp32 partials to g_part[ks][ch][n*128+m]
        float* base = g_part + (ks * 3 + ch) * NGNG;
        #pragma unroll
        for (int mt = 0; mt < 2; mt++) {
            #pragma unroll
            for (int nt = 0; nt < 4; nt++) {
                int m = wm + mt * 16 + quad;
                int n = wn + nt * 8 + 2 * tq;
                base[n * NG + m]           = acc[mt][nt][0];
                base[(n + 1) * NG + m]     = acc[mt][nt][1];
                base[n * NG + m + 8]       = acc[mt][nt][2];
                base[(n + 1) * NG + m + 8] = acc[mt][nt][3];
            }
        }
    }
}

// ---------------------------------------------------------------------------
// Fused reduce: grid 128 x 384 threads. Thread (g, ch) sums 128 slices,
// ch0 shares 1/s0 via smem, normalize, write final output.
// ---------------------------------------------------------------------------
__global__ void __launch_bounds__(384) reduce_kernel(float* __restrict__ out) {
    __shared__ float s_inv[NG];
    int tid = threadIdx.x;
    int gl = tid & 127, ch = tid >> 7;
    int g = blockIdx.x * NG + gl;

    float s = 0.0f;
    const float* p = g_part + ch * NGNG + g;
    #pragma unroll 8
    for (int ks = 0; ks < KSPLIT; ks++, p += 3 * NGNG) s += *p;

    if (ch == 0) s_inv[gl] = 1.0f / s;
    __syncthreads();

    if (ch == 0) out[g] = s;
    else         out[ch * NGNG + g] = s * s_inv[gl];
}

extern "C" void kernel_launch(void* const* d_in, const int* in_sizes, int n_in,
                              void* d_out, int out_size) {
    const float* X = (const float*)d_in[0];
    const float* Y = (const float*)d_in[1];
    float* out = (float*)d_out;

    cudaFuncSetAttribute(main_kernel,
                         cudaFuncAttributeMaxDynamicSharedMemorySize, SMEM_TOTAL);
    main_kernel<<<KSPLIT, 512, SMEM_TOTAL>>>(X, Y);
    reduce_kernel<<<NGNG / NG, 384>>>(out);
}

// round 8
// speedup vs baseline: 1.5775x; 1.0127x over previous
#include <cuda_runtime.h>
#include <cuda_bf16.h>
#include <cstdint>

#define NP 8192
#define NG 128
#define NGNG (NG * NG)
#define KSPLIT 128
#define KSLICE 64
#define NSPLIT2 8

// smem byte offsets (dynamic, 128KB total)
#define A_HI 0
#define A_LO 16384
#define B_T(ch, p) (32768 + ((ch) * 2 + (p)) * 16384)
#define SMEM_TOTAL 131072

__device__ float g_part[KSPLIT * 3 * NGNG];   // [ks][ch][n*128+m]
__device__ float g_p2[3 * NSPLIT2 * NGNG];    // [ch][split][g]

#define SWZ(o) ((o) ^ (((o) >> 3) & 0x70))

__device__ __forceinline__ uint32_t smem_u32(const void* p) {
    uint32_t a;
    asm("{ .reg .u64 t; cvta.to.shared.u64 t, %1; cvt.u32.u64 %0, t; }"
        : "=r"(a) : "l"(p));
    return a;
}
__device__ __forceinline__ void ldsm4(uint32_t& r0, uint32_t& r1,
                                      uint32_t& r2, uint32_t& r3, uint32_t a) {
    asm volatile("ldmatrix.sync.aligned.m8n8.x4.shared.b16 {%0,%1,%2,%3}, [%4];"
                 : "=r"(r0), "=r"(r1), "=r"(r2), "=r"(r3) : "r"(a));
}
__device__ __forceinline__ void mma16816(float* d, const uint32_t* a,
                                         const uint32_t* b) {
    asm volatile(
        "mma.sync.aligned.m16n8k16.row.col.f32.bf16.bf16.f32 "
        "{%0,%1,%2,%3},{%4,%5,%6,%7},{%8,%9},{%0,%1,%2,%3};"
        : "+f"(d[0]), "+f"(d[1]), "+f"(d[2]), "+f"(d[3])
        : "r"(a[0]), "r"(a[1]), "r"(a[2]), "r"(a[3]), "r"(b[0]), "r"(b[1]));
}
__device__ __forceinline__ uint32_t pack_bf16(float a, float b) {
    uint16_t lo = __bfloat16_as_ushort(__float2bfloat16(a));
    uint16_t hi = __bfloat16_as_ushort(__float2bfloat16(b));
    return (uint32_t)lo | ((uint32_t)hi << 16);
}

// ---------------------------------------------------------------------------
// Main: block ks builds A hi/lo once + 3 channel B tables (ey computed once),
// then 3 channels x 3 splits x 4 ksteps of m16n8k16 bf16 HMMA, fp32 accum.
// Grid 128 = one wave. 512 threads, warp grid 4m x 4n, warp tile 32x32.
// (Measured ~8.5us, rel_err 4.9e-7 — unchanged from R7.)
// ---------------------------------------------------------------------------
__global__ void __launch_bounds__(512, 1) main_kernel(
    const float* __restrict__ X, const float* __restrict__ Y) {
    extern __shared__ char smem[];
    uint32_t sb = smem_u32(smem);
    int tid = threadIdx.x, lane = tid & 31, wid = tid >> 5;
    int ks = blockIdx.x;
    int kbeg = ks * KSLICE;

    const float GSTEP = 4.0f / 127.0f;
    const float2* Xv = (const float2*)X;
    const float2* Yv = (const float2*)Y;

    // ---- Build A: Ex[m][k] hi/lo, k-pairs packed, SW128 rows --------------
    #pragma unroll
    for (int it = 0; it < 8; it++) {
        int idx = it * 512 + tid;            // 4096 items: 128 m x 32 kpairs
        int kp = idx & 31, m = idx >> 5;
        int kk = 2 * kp;
        float2 x0 = Xv[kbeg + kk];
        float2 x1 = Xv[kbeg + kk + 1];
        float gm = fmaf((float)m, GSTEP, -2.0f);
        float d0 = gm - x0.x, d1 = gm - x1.x;
        float e0 = __expf(-0.5f * d0 * d0);
        float e1 = __expf(-0.5f * d1 * d1);
        float h0 = __bfloat162float(__float2bfloat16(e0));
        float h1 = __bfloat162float(__float2bfloat16(e1));
        uint32_t sw = SWZ((uint32_t)(m * 128 + kk * 2));
        *(uint32_t*)(smem + A_HI + sw) = pack_bf16(h0, h1);
        *(uint32_t*)(smem + A_LO + sw) = pack_bf16(e0 - h0, e1 - h1);
    }
    // ---- Build B: ey once, 3 channel tables hi/lo --------------------------
    #pragma unroll
    for (int it = 0; it < 8; it++) {
        int idx = it * 512 + tid;            // 4096 items: 128 n x 32 kpairs
        int kp = idx & 31, n = idx >> 5;
        int kk = 2 * kp;
        float2 x0 = Xv[kbeg + kk];
        float2 x1 = Xv[kbeg + kk + 1];
        float2 y0 = Yv[kbeg + kk];
        float2 y1 = Yv[kbeg + kk + 1];
        float gn = fmaf((float)n, GSTEP, -2.0f);
        float d0 = gn - x0.y, d1 = gn - x1.y;
        float e0 = __expf(-0.5f * d0 * d0);
        float e1 = __expf(-0.5f * d1 * d1);
        uint32_t sw = SWZ((uint32_t)(n * 128 + kk * 2));
        float v0[3] = { e0, e0 * y0.x, e0 * y0.y };
        float v1[3] = { e1, e1 * y1.x, e1 * y1.y };
        #pragma unroll
        for (int c = 0; c < 3; c++) {
            float h0 = __bfloat162float(__float2bfloat16(v0[c]));
            float h1 = __bfloat162float(__float2bfloat16(v1[c]));
            *(uint32_t*)(smem + B_T(c, 0) + sw) = pack_bf16(h0, h1);
            *(uint32_t*)(smem + B_T(c, 1) + sw) = pack_bf16(v0[c] - h0, v1[c] - h1);
        }
    }
    __syncthreads();

    // ---- Warp tiling (frag scheme verified in R6/R7) ------------------------
    int wm = (wid & 3) * 32, wn = (wid >> 2) * 32;
    int arow = lane & 15;
    uint32_t acolx = (uint32_t)((lane >> 4) << 4);
    int brow = (lane & 7) + ((lane & 16) ? 8 : 0);
    uint32_t bcolx = (lane & 8) ? 16u : 0u;
    uint32_t axor = (uint32_t)((arow & 7) << 4);
    uint32_t bxor = (uint32_t)((lane & 7) << 4);
    int quad = lane >> 2, tq = lane & 3;

    #pragma unroll 1
    for (int ch = 0; ch < 3; ch++) {
        float acc[2][4][4];
        #pragma unroll
        for (int i = 0; i < 2; i++)
            #pragma unroll
            for (int j = 0; j < 4; j++)
                #pragma unroll
                for (int c = 0; c < 4; c++) acc[i][j][c] = 0.0f;

        #pragma unroll
        for (int split = 0; split < 3; split++) {
            uint32_t Aoff = (split == 2) ? A_LO : A_HI;
            uint32_t Boff = B_T(ch, (split == 1) ? 1 : 0);
            uint32_t ab0 = sb + Aoff + (uint32_t)((wm + arow) * 128);
            uint32_t ab1 = sb + Aoff + (uint32_t)((wm + 16 + arow) * 128);
            uint32_t bb0 = sb + Boff + (uint32_t)((wn + brow) * 128);
            uint32_t bb1 = sb + Boff + (uint32_t)((wn + 16 + brow) * 128);

            #pragma unroll
            for (int kstep = 0; kstep < 4; kstep++) {
                uint32_t acol = (uint32_t)(kstep * 32 + acolx) ^ axor;
                uint32_t bcol = (uint32_t)(kstep * 32 + bcolx) ^ bxor;
                uint32_t a0[4], a1[4], bf[4][2];
                ldsm4(a0[0], a0[1], a0[2], a0[3], ab0 + acol);
                ldsm4(a1[0], a1[1], a1[2], a1[3], ab1 + acol);
                ldsm4(bf[0][0], bf[0][1], bf[1][0], bf[1][1], bb0 + bcol);
                ldsm4(bf[2][0], bf[2][1], bf[3][0], bf[3][1], bb1 + bcol);
                #pragma unroll
                for (int nt = 0; nt < 4; nt++) {
                    mma16816(acc[0][nt], a0, bf[nt]);
                    mma16816(acc[1][nt], a1, bf[nt]);
                }
            }
        }

        // Epilogue: fp32 partials to g_part[ks][ch][n*128+m]
        float* base = g_part + (ks * 3 + ch) * NGNG;
        #pragma unroll
        for (int mt = 0; mt < 2; mt++) {
            #pragma unroll
            for (int nt = 0; nt < 4; nt++) {
                int m = wm + mt * 16 + quad;
                int n = wn + nt * 8 + 2 * tq;
                base[n * NG + m]           = acc[mt][nt][0];
                base[(n + 1) * NG + m]     = acc[mt][nt][1];
                base[n * NG + m + 8]       = acc[mt][nt][2];
                base[(n + 1) * NG + m + 8] = acc[mt][nt][3];
            }
        }
    }
}

// ---------------------------------------------------------------------------
// Reduce stage 1: 131072 threads (8 splits x 16384 g); thread sums 16 slices
// x 3 channels. Wide + MLP=3 -> BW-bound, not latency-bound (R3-proven).
// ---------------------------------------------------------------------------
__global__ void __launch_bounds__(256) reduce1_kernel() {
    int idx = blockIdx.x * 256 + threadIdx.x;
    int g = idx & (NGNG - 1);
    int s = idx >> 14;
    int b0 = s * (KSPLIT / NSPLIT2);

    float s0 = 0.0f, s1 = 0.0f, s2 = 0.0f;
    const float* p = g_part + b0 * 3 * NGNG + g;
    #pragma unroll 4
    for (int k = 0; k < KSPLIT / NSPLIT2; k++, p += 3 * NGNG) {
        s0 += p[0];
        s1 += p[NGNG];
        s2 += p[2 * NGNG];
    }
    g_p2[(0 * NSPLIT2 + s) * NGNG + g] = s0;
    g_p2[(1 * NSPLIT2 + s) * NGNG + g] = s1;
    g_p2[(2 * NSPLIT2 + s) * NGNG + g] = s2;
}

// ---------------------------------------------------------------------------
// Reduce stage 2: 16384 threads; sum 8 splits per channel, normalize, write.
// ---------------------------------------------------------------------------
__global__ void __launch_bounds__(256) reduce2_kernel(float* __restrict__ out) {
    int g = blockIdx.x * 256 + threadIdx.x;
    float t0 = 0.0f, t1 = 0.0f, t2 = 0.0f;
    #pragma unroll
    for (int s = 0; s < NSPLIT2; s++) {
        t0 += g_p2[(0 * NSPLIT2 + s) * NGNG + g];
        t1 += g_p2[(1 * NSPLIT2 + s) * NGNG + g];
        t2 += g_p2[(2 * NSPLIT2 + s) * NGNG + g];
    }
    float inv = 1.0f / t0;
    out[g]            = t0;
    out[NGNG + g]     = t1 * inv;
    out[2 * NGNG + g] = t2 * inv;
}

extern "C" void kernel_launch(void* const* d_in, const int* in_sizes, int n_in,
                              void* d_out, int out_size) {
    const float* X = (const float*)d_in[0];
    const float* Y = (const float*)d_in[1];
    float* out = (float*)d_out;

    cudaFuncSetAttribute(main_kernel,
                         cudaFuncAttributeMaxDynamicSharedMemorySize, SMEM_TOTAL);
    main_kernel<<<KSPLIT, 512, SMEM_TOTAL>>>(X, Y);
    reduce1_kernel<<<NSPLIT2 * NGNG / 256, 256>>>();
    reduce2_kernel<<<NGNG / 256, 256>>>(out);
}